// round 1
// baseline (speedup 1.0000x reference)
#include <cuda_runtime.h>
#include <math.h>

#define MTOT 32768   // B*N rows
#define DDIM 1024
#define HDIM 256
#define ADIM 128
#define BB   16
#define NN   2048
#define NEGV (-1e9f)

// Scratch (allocation-free rule: __device__ globals)
__device__ float g_h[(size_t)MTOT * HDIM];   // pre-LN h, then activated in place
__device__ float g_logits[MTOT];

// ---------------------------------------------------------------------------
// packed fp32x2 FMA (Blackwell 2x fp32 path; ptxas never emits it from C++)
// ---------------------------------------------------------------------------
__device__ __forceinline__ void fma2(unsigned long long& d,
                                     unsigned long long a,
                                     unsigned long long b) {
    asm("fma.rn.f32x2 %0, %1, %2, %0;" : "+l"(d) : "l"(a), "l"(b));
}
__device__ __forceinline__ unsigned long long dup2(float v) {
    unsigned long long r;
    unsigned int u = __float_as_uint(v);
    asm("mov.b64 %0, {%1, %1};" : "=l"(r) : "r"(u));
    return r;
}

// ---------------------------------------------------------------------------
// Kernel 1: h_pre = x @ W1^T + b1     (M=32768, N=256, K=1024)
// BM=128, BN=128, BK=8, 256 threads, per-thread 8x8 via 4 f32x2-pairs x 8
// ---------------------------------------------------------------------------
__global__ __launch_bounds__(256) void gemm1_kernel(
        const float* __restrict__ x, const float* __restrict__ W1,
        const float* __restrict__ b1) {
    __shared__ __align__(16) float As[8][128];
    __shared__ __align__(16) float Bs[8][128];
    const int tid = threadIdx.x;
    const int bm = blockIdx.y * 128;
    const int bn = blockIdx.x * 128;
    const int tr = tid >> 4, tc = tid & 15;
    const int mBase = tr * 8, nBase = tc * 8;

    unsigned long long acc[4][8];
    for (int i = 0; i < 4; i++)
        for (int j = 0; j < 8; j++) acc[i][j] = 0ull;

    const int lr = tid >> 1;            // 0..127
    const int lk = (tid & 1) * 4;       // 0 or 4
    const float* xp = x  + (size_t)(bm + lr) * DDIM + lk;
    const float* wp = W1 + (size_t)(bn + lr) * DDIM + lk;

    for (int k0 = 0; k0 < DDIM; k0 += 8) {
        float4 av = *(const float4*)(xp + k0);
        float4 bv = *(const float4*)(wp + k0);
        As[lk + 0][lr] = av.x; As[lk + 1][lr] = av.y;
        As[lk + 2][lr] = av.z; As[lk + 3][lr] = av.w;
        Bs[lk + 0][lr] = bv.x; Bs[lk + 1][lr] = bv.y;
        Bs[lk + 2][lr] = bv.z; Bs[lk + 3][lr] = bv.w;
        __syncthreads();
        #pragma unroll
        for (int k = 0; k < 8; k++) {
            unsigned long long a2[4];
            const unsigned long long* ap =
                (const unsigned long long*)&As[k][mBase];
            a2[0] = ap[0]; a2[1] = ap[1]; a2[2] = ap[2]; a2[3] = ap[3];
            float bq[8];
            *(float4*)(bq)     = *(const float4*)&Bs[k][nBase];
            *(float4*)(bq + 4) = *(const float4*)&Bs[k][nBase + 4];
            #pragma unroll
            for (int j = 0; j < 8; j++) {
                unsigned long long b2 = dup2(bq[j]);
                fma2(acc[0][j], a2[0], b2);
                fma2(acc[1][j], a2[1], b2);
                fma2(acc[2][j], a2[2], b2);
                fma2(acc[3][j], a2[3], b2);
            }
        }
        __syncthreads();
    }
    #pragma unroll
    for (int i = 0; i < 4; i++) {
        const int m0 = bm + mBase + 2 * i;
        #pragma unroll
        for (int j = 0; j < 8; j++) {
            const int n = bn + nBase + j;
            const float bias = b1[n];
            const unsigned long long u = acc[i][j];
            const float lo = __uint_as_float((unsigned int)(u & 0xffffffffull));
            const float hi = __uint_as_float((unsigned int)(u >> 32));
            g_h[(size_t)m0 * HDIM + n]       = lo + bias;
            g_h[(size_t)(m0 + 1) * HDIM + n] = hi + bias;
        }
    }
}

// ---------------------------------------------------------------------------
// Kernel 2: per-row LayerNorm + exact GELU (in place) + instance score
// one warp per row; scores go directly into d_out[BB + m]
// ---------------------------------------------------------------------------
__global__ __launch_bounds__(256) void ln_gelu_score_kernel(
        const float* __restrict__ ln_g, const float* __restrict__ ln_b,
        const float* __restrict__ Wc, const float* __restrict__ bc,
        float* __restrict__ out) {
    const int warp = threadIdx.x >> 5, lane = threadIdx.x & 31;
    const int m = blockIdx.x * 8 + warp;
    float* row = g_h + (size_t)m * HDIM;

    float4 v0 = *(float4*)(row + lane * 4);
    float4 v1 = *(float4*)(row + 128 + lane * 4);
    float s = v0.x + v0.y + v0.z + v0.w + v1.x + v1.y + v1.z + v1.w;
    float q = v0.x * v0.x + v0.y * v0.y + v0.z * v0.z + v0.w * v0.w
            + v1.x * v1.x + v1.y * v1.y + v1.z * v1.z + v1.w * v1.w;
    #pragma unroll
    for (int o = 16; o; o >>= 1) {
        s += __shfl_xor_sync(0xffffffffu, s, o);
        q += __shfl_xor_sync(0xffffffffu, q, o);
    }
    const float mean = s * (1.0f / 256.0f);
    const float var  = q * (1.0f / 256.0f) - mean * mean;
    const float rstd = rsqrtf(var + 1e-5f);

    float4 g0 = *(const float4*)(ln_g + lane * 4);
    float4 g1 = *(const float4*)(ln_g + 128 + lane * 4);
    float4 e0 = *(const float4*)(ln_b + lane * 4);
    float4 e1 = *(const float4*)(ln_b + 128 + lane * 4);
    float4 w0 = *(const float4*)(Wc + lane * 4);
    float4 w1 = *(const float4*)(Wc + 128 + lane * 4);

    float va[8] = {v0.x, v0.y, v0.z, v0.w, v1.x, v1.y, v1.z, v1.w};
    float ga[8] = {g0.x, g0.y, g0.z, g0.w, g1.x, g1.y, g1.z, g1.w};
    float ba[8] = {e0.x, e0.y, e0.z, e0.w, e1.x, e1.y, e1.z, e1.w};
    float wa[8] = {w0.x, w0.y, w0.z, w0.w, w1.x, w1.y, w1.z, w1.w};

    float sc = 0.0f;
    #pragma unroll
    for (int i = 0; i < 8; i++) {
        float y = (va[i] - mean) * rstd * ga[i] + ba[i];
        y = 0.5f * y * (1.0f + erff(y * 0.70710678118654752f));  // exact GELU
        va[i] = y;
        sc += y * wa[i];
    }
    float4 o0 = {va[0], va[1], va[2], va[3]};
    float4 o1 = {va[4], va[5], va[6], va[7]};
    *(float4*)(row + lane * 4) = o0;
    *(float4*)(row + 128 + lane * 4) = o1;

    #pragma unroll
    for (int o = 16; o; o >>= 1) sc += __shfl_xor_sync(0xffffffffu, sc, o);
    if (lane == 0) out[BB + m] = sc + bc[0];
}

// ---------------------------------------------------------------------------
// Kernel 3: attn_logits = tanh(h @ Wa1^T + ba1) . Wa2 + ba2
// GEMM M=32768, N=128(full), K=256; BM=64, BK=16; fused epilogue row-reduce
// ---------------------------------------------------------------------------
__global__ __launch_bounds__(256) void gemm2_kernel(
        const float* __restrict__ Wa1, const float* __restrict__ ba1,
        const float* __restrict__ Wa2, const float* __restrict__ ba2) {
    __shared__ __align__(16) float As[16][64];
    __shared__ __align__(16) float Bs[16][128];
    const int tid = threadIdx.x;
    const int bm = blockIdx.x * 64;
    const int tr = tid >> 4, tc = tid & 15;
    const int mBase = tr * 4, nBase = tc * 8;

    float acc[4][8];
    for (int i = 0; i < 4; i++)
        for (int j = 0; j < 8; j++) acc[i][j] = 0.0f;

    const int ar = tid >> 2, ak = (tid & 3) * 4;     // A: 64 rows x 16k
    const int brn = tid >> 1, bk = (tid & 1) * 8;    // B: 128 rows x 16k

    for (int k0 = 0; k0 < HDIM; k0 += 16) {
        float4 av = *(const float4*)&g_h[(size_t)(bm + ar) * HDIM + k0 + ak];
        As[ak + 0][ar] = av.x; As[ak + 1][ar] = av.y;
        As[ak + 2][ar] = av.z; As[ak + 3][ar] = av.w;
        float4 b0 = *(const float4*)&Wa1[(size_t)brn * HDIM + k0 + bk];
        float4 b1v = *(const float4*)&Wa1[(size_t)brn * HDIM + k0 + bk + 4];
        Bs[bk + 0][brn] = b0.x;  Bs[bk + 1][brn] = b0.y;
        Bs[bk + 2][brn] = b0.z;  Bs[bk + 3][brn] = b0.w;
        Bs[bk + 4][brn] = b1v.x; Bs[bk + 5][brn] = b1v.y;
        Bs[bk + 6][brn] = b1v.z; Bs[bk + 7][brn] = b1v.w;
        __syncthreads();
        #pragma unroll
        for (int k = 0; k < 16; k++) {
            float a[4];
            *(float4*)a = *(const float4*)&As[k][mBase];
            float bq[8];
            *(float4*)(bq)     = *(const float4*)&Bs[k][nBase];
            *(float4*)(bq + 4) = *(const float4*)&Bs[k][nBase + 4];
            #pragma unroll
            for (int j = 0; j < 8; j++)
                #pragma unroll
                for (int i = 0; i < 4; i++) acc[i][j] += a[i] * bq[j];
        }
        __syncthreads();
    }
    // epilogue: tanh, weight by Wa2, reduce over n
    float part[4] = {0.f, 0.f, 0.f, 0.f};
    #pragma unroll
    for (int j = 0; j < 8; j++) {
        const int n = nBase + j;
        const float w2 = Wa2[n];
        const float bb = ba1[n];
        #pragma unroll
        for (int i = 0; i < 4; i++)
            part[i] += tanhf(acc[i][j] + bb) * w2;
    }
    #pragma unroll
    for (int off = 8; off; off >>= 1)
        #pragma unroll
        for (int i = 0; i < 4; i++)
            part[i] += __shfl_xor_sync(0xffffffffu, part[i], off);
    if (tc == 0) {
        const float b2 = ba2[0];
        #pragma unroll
        for (int i = 0; i < 4; i++)
            g_logits[bm + mBase + i] = part[i] + b2;
    }
}

// ---------------------------------------------------------------------------
// Kernel 4: per-batch masked softmax pooling + dynamic top-k mean
// ---------------------------------------------------------------------------
__device__ __forceinline__ float block_sum(float v, float* red) {
    const int lane = threadIdx.x & 31, warp = threadIdx.x >> 5;
    #pragma unroll
    for (int o = 16; o; o >>= 1) v += __shfl_xor_sync(0xffffffffu, v, o);
    __syncthreads();
    if (lane == 0) red[warp] = v;
    __syncthreads();
    if (warp == 0) {
        float t = red[lane];
        #pragma unroll
        for (int o = 16; o; o >>= 1) t += __shfl_xor_sync(0xffffffffu, t, o);
        if (lane == 0) red[0] = t;
    }
    __syncthreads();
    return red[0];
}
__device__ __forceinline__ float block_max(float v, float* red) {
    const int lane = threadIdx.x & 31, warp = threadIdx.x >> 5;
    #pragma unroll
    for (int o = 16; o; o >>= 1)
        v = fmaxf(v, __shfl_xor_sync(0xffffffffu, v, o));
    __syncthreads();
    if (lane == 0) red[warp] = v;
    __syncthreads();
    if (warp == 0) {
        float t = red[lane];
        #pragma unroll
        for (int o = 16; o; o >>= 1)
            t = fmaxf(t, __shfl_xor_sync(0xffffffffu, t, o));
        if (lane == 0) red[0] = t;
    }
    __syncthreads();
    return red[0];
}

__global__ __launch_bounds__(1024) void finalize_kernel(
        const int* __restrict__ lengths, float* __restrict__ out) {
    __shared__ float s_sc[NN];
    __shared__ float s_red[32];
    const int b = blockIdx.x, tid = threadIdx.x;
    const int T = lengths[b];
    const float* scores = out + BB + (size_t)b * NN;
    const float* logits = g_logits + (size_t)b * NN;

    const float sc0 = scores[tid],        sc1 = scores[tid + 1024];
    const float lg0 = logits[tid],        lg1 = logits[tid + 1024];
    const bool  v0  = tid < T,            v1  = (tid + 1024) < T;
    const float ml0 = v0 ? lg0 : NEGV,    ml1 = v1 ? lg1 : NEGV;

    const float mx  = block_max(fmaxf(ml0, ml1), s_red);
    const float e0  = expf(ml0 - mx), e1 = expf(ml1 - mx);
    const float den = block_sum(e0 + e1, s_red);
    const float num = block_sum((v0 ? e0 * sc0 : 0.0f) +
                                (v1 ? e1 * sc1 : 0.0f), s_red);
    const float attn = num / den;

    // exact dynamic top-k via full bitonic sort (ascending)
    s_sc[tid]        = v0 ? sc0 : NEGV;
    s_sc[tid + 1024] = v1 ? sc1 : NEGV;
    for (int k2 = 2; k2 <= NN; k2 <<= 1) {
        for (int j = k2 >> 1; j > 0; j >>= 1) {
            __syncthreads();
            #pragma unroll 1
            for (int i = tid; i < NN; i += 1024) {
                const int ixj = i ^ j;
                if (ixj > i) {
                    const float a = s_sc[i], c = s_sc[ixj];
                    const bool up = ((i & k2) == 0);
                    if ((a > c) == up) { s_sc[i] = c; s_sc[ixj] = a; }
                }
            }
        }
    }
    __syncthreads();

    int k = T / 10;
    if (k < 1) k = 1;
    float ts = 0.0f;
    if (tid < k) ts = s_sc[NN - 1 - tid];
    const float tsum = block_sum(ts, s_red);

    if (tid == 0)
        out[b] = (T > 0) ? 0.5f * attn + 0.5f * (tsum / (float)k) : 0.0f;
}

// ---------------------------------------------------------------------------
extern "C" void kernel_launch(void* const* d_in, const int* in_sizes, int n_in,
                              void* d_out, int out_size) {
    const float* x    = (const float*)d_in[0];
    const int*   lens = (const int*)  d_in[1];
    const float* W1   = (const float*)d_in[2];
    const float* b1   = (const float*)d_in[3];
    const float* ln_g = (const float*)d_in[4];
    const float* ln_b = (const float*)d_in[5];
    const float* Wa1  = (const float*)d_in[6];
    const float* ba1  = (const float*)d_in[7];
    const float* Wa2  = (const float*)d_in[8];
    const float* ba2  = (const float*)d_in[9];
    const float* Wc   = (const float*)d_in[10];
    const float* bc   = (const float*)d_in[11];
    float* out = (float*)d_out;

    dim3 g1(HDIM / 128, MTOT / 128);
    gemm1_kernel<<<g1, 256>>>(x, W1, b1);
    ln_gelu_score_kernel<<<MTOT / 8, 256>>>(ln_g, ln_b, Wc, bc, out);
    gemm2_kernel<<<MTOT / 64, 256>>>(Wa1, ba1, Wa2, ba2);
    finalize_kernel<<<BB, 1024>>>(lens, out);
}

// round 5
// speedup vs baseline: 2.6277x; 2.6277x over previous
#include <cuda_runtime.h>
#include <cuda_bf16.h>
#include <math.h>
#include <cstdint>

#define MTOT 32768   // B*N rows
#define DDIM 1024
#define HDIM 256
#define ADIM 128
#define BB   16
#define NN   2048
#define NEGV (-1e9f)

// ---------------------------------------------------------------------------
// Scratch (__device__ globals; allocation-free rule)
// ---------------------------------------------------------------------------
__device__ __align__(1024) __nv_bfloat16 g_whi[(size_t)HDIM * DDIM];
__device__ __align__(1024) __nv_bfloat16 g_wlo[(size_t)HDIM * DDIM];
__device__ __align__(1024) __nv_bfloat16 g_wahi[(size_t)ADIM * HDIM];
__device__ __align__(1024) __nv_bfloat16 g_walo[(size_t)ADIM * HDIM];
__device__ __align__(1024) __nv_bfloat16 g_hhi[(size_t)MTOT * HDIM];
__device__ __align__(1024) __nv_bfloat16 g_hlo[(size_t)MTOT * HDIM];
__device__ __align__(1024) float g_logits[MTOT];

// ---------------------------------------------------------------------------
// Helpers (base sm_100 target: mma.sync / ldmatrix / cp.async only)
// ---------------------------------------------------------------------------
__device__ __forceinline__ uint32_t smem_u32(const void* p) {
    uint32_t r;
    asm("{ .reg .u64 t; cvta.to.shared.u64 t, %1; cvt.u32.u64 %0, t; }"
        : "=r"(r) : "l"(p));
    return r;
}
__device__ __forceinline__ void cpa16(uint32_t dst, const void* src) {
    asm volatile("cp.async.cg.shared.global [%0], [%1], 16;"
                 :: "r"(dst), "l"(src) : "memory");
}
#define CP_COMMIT() asm volatile("cp.async.commit_group;" ::: "memory")
#define CP_WAIT0()  asm volatile("cp.async.wait_group 0;" ::: "memory")

__device__ __forceinline__ void ldsm4(uint32_t* r, uint32_t a) {
    asm volatile("ldmatrix.sync.aligned.m8n8.x4.shared.b16 {%0,%1,%2,%3}, [%4];"
                 : "=r"(r[0]), "=r"(r[1]), "=r"(r[2]), "=r"(r[3]) : "r"(a));
}
__device__ __forceinline__ void mmabf(float* c, const uint32_t* a,
                                      uint32_t b0, uint32_t b1) {
    asm volatile(
        "mma.sync.aligned.m16n8k16.row.col.f32.bf16.bf16.f32 "
        "{%0,%1,%2,%3}, {%4,%5,%6,%7}, {%8,%9}, {%0,%1,%2,%3};"
        : "+f"(c[0]), "+f"(c[1]), "+f"(c[2]), "+f"(c[3])
        : "r"(a[0]), "r"(a[1]), "r"(a[2]), "r"(a[3]), "r"(b0), "r"(b1));
}
__device__ __forceinline__ uint32_t sw64(uint32_t off) {
    return off ^ ((off >> 3) & 0x30);
}
__device__ __forceinline__ uint32_t pkbf2(__nv_bfloat16 a, __nv_bfloat16 b) {
    __nv_bfloat162 t = __halves2bfloat162(a, b);   // .x = a = low 16 bits
    return *reinterpret_cast<uint32_t*>(&t);
}
__device__ __forceinline__ float gelu_exact(float y) {
    return 0.5f * y * (1.0f + erff(y * 0.70710678118654752f));
}

// ---------------------------------------------------------------------------
// Weight conversion: f32 -> bf16 hi/lo split (tiny kernels)
// ---------------------------------------------------------------------------
__device__ __forceinline__ void cvt_store(float4 v, __nv_bfloat16* hi,
                                          __nv_bfloat16* lo, size_t i) {
    __nv_bfloat16 h0 = __float2bfloat16(v.x), h1 = __float2bfloat16(v.y),
                  h2 = __float2bfloat16(v.z), h3 = __float2bfloat16(v.w);
    __nv_bfloat16 l0 = __float2bfloat16(v.x - __bfloat162float(h0));
    __nv_bfloat16 l1 = __float2bfloat16(v.y - __bfloat162float(h1));
    __nv_bfloat16 l2 = __float2bfloat16(v.z - __bfloat162float(h2));
    __nv_bfloat16 l3 = __float2bfloat16(v.w - __bfloat162float(h3));
    reinterpret_cast<__nv_bfloat162*>(hi)[2 * i]     = __halves2bfloat162(h0, h1);
    reinterpret_cast<__nv_bfloat162*>(hi)[2 * i + 1] = __halves2bfloat162(h2, h3);
    reinterpret_cast<__nv_bfloat162*>(lo)[2 * i]     = __halves2bfloat162(l0, l1);
    reinterpret_cast<__nv_bfloat162*>(lo)[2 * i + 1] = __halves2bfloat162(l2, l3);
}
__global__ __launch_bounds__(256) void convert_w1_kernel(const float* __restrict__ s) {
    size_t i = (size_t)blockIdx.x * 256 + threadIdx.x;
    cvt_store(reinterpret_cast<const float4*>(s)[i], g_whi, g_wlo, i);
}
__global__ __launch_bounds__(256) void convert_wa_kernel(const float* __restrict__ s) {
    size_t i = (size_t)blockIdx.x * 256 + threadIdx.x;
    cvt_store(reinterpret_cast<const float4*>(s)[i], g_wahi, g_walo, i);
}

// ---------------------------------------------------------------------------
// GEMM1 + LN + GELU + instance score, fused.
// C = x(32768x1024) @ W1^T(1024x256): BM=64, BN=256(full), KC=32, 256 thr.
// bf16 2-term split: acc += xh*wh + xh*wl + xl*wh  (fp32 accum via mma.sync)
// Per-stage smem: Ahi[0,4K) Alo[4K,8K) Bhi[8K,24K) Blo[24K,40K)
// ---------------------------------------------------------------------------
#define ST1 40960
#define SM1 (2 * ST1)

__device__ __forceinline__ void cp_w1(uint32_t sb, int c) {
    const int t = threadIdx.x;
    #pragma unroll
    for (int i = 0; i < 4; i++) {
        int a = t + i * 256;           // atom 0..1023: 256 n-rows x 4 atoms
        int row = a >> 2, ac = a & 3;
        uint32_t sw = sw64(row * 64 + ac * 16);
        const __nv_bfloat16* ph = g_whi + (size_t)row * DDIM + c * 32 + ac * 8;
        const __nv_bfloat16* pl = g_wlo + (size_t)row * DDIM + c * 32 + ac * 8;
        cpa16(sb + 8192 + sw, ph);
        cpa16(sb + 24576 + sw, pl);
    }
}

__global__ __launch_bounds__(256, 1) void gemm1_kernel(
        const float* __restrict__ x, const float* __restrict__ b1,
        const float* __restrict__ ln_g, const float* __restrict__ ln_b,
        const float* __restrict__ Wc, const float* __restrict__ bc,
        float* __restrict__ out) {
    extern __shared__ __align__(1024) char smem[];
    const uint32_t sbu = smem_u32(smem);
    const int tid = threadIdx.x, lane = tid & 31, wid = tid >> 5;
    const int bm = blockIdx.x * 64;
    const int arow = tid >> 2, akq = (tid & 3) * 8;   // A-load mapping

    float4 ra, rb;
    {   // prologue: chunk 0
        const float* src = x + (size_t)(bm + arow) * DDIM + akq;
        ra = *(const float4*)src; rb = *(const float4*)(src + 4);
        cp_w1(sbu, 0);
        CP_COMMIT();
    }

    float acc[4][4][4];
    #pragma unroll
    for (int i = 0; i < 4; i++)
        #pragma unroll
        for (int j = 0; j < 4; j++)
            #pragma unroll
            for (int k = 0; k < 4; k++) acc[i][j][k] = 0.0f;

    const int n0 = wid * 32;

    for (int c = 0; c < 32; c++) {
        const uint32_t stg = (uint32_t)(c & 1) * ST1;
        {   // convert+store A for chunk c (regs were prefetched)
            uint32_t off = sw64(arow * 64 + (tid & 3) * 16);
            float va[8] = {ra.x, ra.y, ra.z, ra.w, rb.x, rb.y, rb.z, rb.w};
            uint4 hv, lv;
            uint32_t* hp = (uint32_t*)&hv;
            uint32_t* lp = (uint32_t*)&lv;
            #pragma unroll
            for (int j = 0; j < 4; j++) {
                float a = va[2 * j], b = va[2 * j + 1];
                __nv_bfloat16 ha = __float2bfloat16(a), hb = __float2bfloat16(b);
                hp[j] = pkbf2(ha, hb);
                lp[j] = pkbf2(__float2bfloat16(a - __bfloat162float(ha)),
                              __float2bfloat16(b - __bfloat162float(hb)));
            }
            *(uint4*)(smem + stg + off) = hv;
            *(uint4*)(smem + stg + 4096 + off) = lv;
        }
        CP_WAIT0();
        __syncthreads();
        if (c < 31) {   // prefetch chunk c+1
            const float* src = x + (size_t)(bm + arow) * DDIM + (c + 1) * 32 + akq;
            ra = *(const float4*)src; rb = *(const float4*)(src + 4);
            cp_w1(sbu + (uint32_t)((c & 1) ^ 1) * ST1, c + 1);
            CP_COMMIT();
        }
        #pragma unroll
        for (int k16 = 0; k16 < 2; k16++) {
            uint32_t aH[4][4], aL[4][4], bH[2][4], bL[2][4];
            #pragma unroll
            for (int mt = 0; mt < 4; mt++) {
                uint32_t off = (uint32_t)((mt * 16 + ((lane >> 3) & 1) * 8 + (lane & 7)) * 64
                               + k16 * 32 + ((lane >> 4) & 1) * 16);
                uint32_t sw = sw64(off);
                ldsm4(aH[mt], sbu + stg + sw);
                ldsm4(aL[mt], sbu + stg + 4096 + sw);
            }
            #pragma unroll
            for (int bp = 0; bp < 2; bp++) {
                uint32_t off = (uint32_t)((n0 + bp * 16 + ((lane >> 4) & 1) * 8 + (lane & 7)) * 64
                               + k16 * 32 + ((lane >> 3) & 1) * 16);
                uint32_t sw = sw64(off);
                ldsm4(bH[bp], sbu + stg + 8192 + sw);
                ldsm4(bL[bp], sbu + stg + 24576 + sw);
            }
            #pragma unroll
            for (int mt = 0; mt < 4; mt++)
                #pragma unroll
                for (int nt = 0; nt < 4; nt++) {
                    uint32_t h0 = bH[nt >> 1][(nt & 1) * 2];
                    uint32_t h1 = bH[nt >> 1][(nt & 1) * 2 + 1];
                    uint32_t l0 = bL[nt >> 1][(nt & 1) * 2];
                    uint32_t l1 = bL[nt >> 1][(nt & 1) * 2 + 1];
                    mmabf(acc[mt][nt], aH[mt], h0, h1);
                    mmabf(acc[mt][nt], aH[mt], l0, l1);
                    mmabf(acc[mt][nt], aL[mt], h0, h1);
                }
        }
    }
    __syncthreads();

    // ---- epilogue: stage accums (64 x 256, stride 260), per-row LN+GELU ----
    float* sacc = (float*)smem;
    #pragma unroll
    for (int mt = 0; mt < 4; mt++)
        #pragma unroll
        for (int nt = 0; nt < 4; nt++) {
            int row = mt * 16 + (lane >> 2);
            int col = n0 + nt * 8 + (lane & 3) * 2;
            sacc[row * 260 + col]           = acc[mt][nt][0];
            sacc[row * 260 + col + 1]       = acc[mt][nt][1];
            sacc[(row + 8) * 260 + col]     = acc[mt][nt][2];
            sacc[(row + 8) * 260 + col + 1] = acc[mt][nt][3];
        }
    __syncthreads();

    #pragma unroll 1
    for (int it = 0; it < 8; it++) {
        const int row = it * 8 + wid;
        const int grow = bm + row;
        float v[8], s = 0.0f, q = 0.0f;
        #pragma unroll
        for (int i = 0; i < 8; i++) {
            int col = lane + 32 * i;
            v[i] = sacc[row * 260 + col] + __ldg(b1 + col);
            s += v[i]; q += v[i] * v[i];
        }
        #pragma unroll
        for (int o = 16; o; o >>= 1) {
            s += __shfl_xor_sync(0xffffffffu, s, o);
            q += __shfl_xor_sync(0xffffffffu, q, o);
        }
        const float mean = s * (1.0f / 256.0f);
        const float var  = q * (1.0f / 256.0f) - mean * mean;
        const float rstd = rsqrtf(var + 1e-5f);
        float sc = 0.0f;
        #pragma unroll
        for (int i = 0; i < 8; i++) {
            int col = lane + 32 * i;
            float y = (v[i] - mean) * rstd * __ldg(ln_g + col) + __ldg(ln_b + col);
            y = gelu_exact(y);
            sc += y * __ldg(Wc + col);
            __nv_bfloat16 hi = __float2bfloat16(y);
            __nv_bfloat16 lo = __float2bfloat16(y - __bfloat162float(hi));
            g_hhi[(size_t)grow * HDIM + col] = hi;
            g_hlo[(size_t)grow * HDIM + col] = lo;
        }
        #pragma unroll
        for (int o = 16; o; o >>= 1) sc += __shfl_xor_sync(0xffffffffu, sc, o);
        if (lane == 0) out[BB + grow] = sc + __ldg(bc);
    }
}

// ---------------------------------------------------------------------------
// GEMM2 + tanh + Wa2 reduce, fused.  logits = tanh(h@Wa1^T + ba1).Wa2 + ba2
// M=32768, N=128(full), K=256: BM=64, BN=128, KC=32, 256 thr (2m x 4n warps)
// Per-stage smem: Ahi[0,4K) Alo[4K,8K) Bhi[8K,16K) Blo[16K,24K)
// ---------------------------------------------------------------------------
#define ST2 24576
#define SM2 (2 * ST2)

__device__ __forceinline__ void cp_h2(uint32_t sb, int c, int bm) {
    const int t = threadIdx.x;
    {   // A: 64 rows x 4 atoms = 256
        int row = t >> 2, ac = t & 3;
        uint32_t sw = sw64(row * 64 + ac * 16);
        cpa16(sb + sw,        g_hhi + (size_t)(bm + row) * HDIM + c * 32 + ac * 8);
        cpa16(sb + 4096 + sw, g_hlo + (size_t)(bm + row) * HDIM + c * 32 + ac * 8);
    }
    #pragma unroll
    for (int i = 0; i < 2; i++) {      // B: 128 rows x 4 atoms = 512
        int a = t + i * 256;
        int row = a >> 2, ac = a & 3;
        uint32_t sw = sw64(row * 64 + ac * 16);
        cpa16(sb + 8192 + sw,  g_wahi + (size_t)row * HDIM + c * 32 + ac * 8);
        cpa16(sb + 16384 + sw, g_walo + (size_t)row * HDIM + c * 32 + ac * 8);
    }
}

__global__ __launch_bounds__(256, 1) void gemm2_kernel(
        const float* __restrict__ ba1, const float* __restrict__ Wa2,
        const float* __restrict__ ba2) {
    extern __shared__ __align__(1024) char smem[];
    const uint32_t sbu = smem_u32(smem);
    const int tid = threadIdx.x, lane = tid & 31, wid = tid >> 5;
    const int bm = blockIdx.x * 64;
    const int m0 = (wid >> 2) * 32, n0 = (wid & 3) * 32;

    cp_h2(sbu, 0, bm);
    CP_COMMIT();

    float acc[2][4][4];
    #pragma unroll
    for (int i = 0; i < 2; i++)
        #pragma unroll
        for (int j = 0; j < 4; j++)
            #pragma unroll
            for (int k = 0; k < 4; k++) acc[i][j][k] = 0.0f;

    for (int c = 0; c < 8; c++) {
        const uint32_t stg = (uint32_t)(c & 1) * ST2;
        CP_WAIT0();
        __syncthreads();
        if (c < 7) {
            cp_h2(sbu + (uint32_t)((c & 1) ^ 1) * ST2, c + 1, bm);
            CP_COMMIT();
        }
        #pragma unroll
        for (int k16 = 0; k16 < 2; k16++) {
            uint32_t aH[2][4], aL[2][4], bH[2][4], bL[2][4];
            #pragma unroll
            for (int mt = 0; mt < 2; mt++) {
                uint32_t off = (uint32_t)((m0 + mt * 16 + ((lane >> 3) & 1) * 8 + (lane & 7)) * 64
                               + k16 * 32 + ((lane >> 4) & 1) * 16);
                uint32_t sw = sw64(off);
                ldsm4(aH[mt], sbu + stg + sw);
                ldsm4(aL[mt], sbu + stg + 4096 + sw);
            }
            #pragma unroll
            for (int bp = 0; bp < 2; bp++) {
                uint32_t off = (uint32_t)((n0 + bp * 16 + ((lane >> 4) & 1) * 8 + (lane & 7)) * 64
                               + k16 * 32 + ((lane >> 3) & 1) * 16);
                uint32_t sw = sw64(off);
                ldsm4(bH[bp], sbu + stg + 8192 + sw);
                ldsm4(bL[bp], sbu + stg + 16384 + sw);
            }
            #pragma unroll
            for (int mt = 0; mt < 2; mt++)
                #pragma unroll
                for (int nt = 0; nt < 4; nt++) {
                    uint32_t h0 = bH[nt >> 1][(nt & 1) * 2];
                    uint32_t h1 = bH[nt >> 1][(nt & 1) * 2 + 1];
                    uint32_t l0 = bL[nt >> 1][(nt & 1) * 2];
                    uint32_t l1 = bL[nt >> 1][(nt & 1) * 2 + 1];
                    mmabf(acc[mt][nt], aH[mt], h0, h1);
                    mmabf(acc[mt][nt], aH[mt], l0, l1);
                    mmabf(acc[mt][nt], aL[mt], h0, h1);
                }
        }
    }
    __syncthreads();

    // ---- epilogue: tanh(.+ba1)*Wa2, reduce over n, cross-warp via smem ----
    float* spart = (float*)smem;   // [64][5] padded
    #pragma unroll
    for (int mt = 0; mt < 2; mt++) {
        float r0 = 0.0f, r1 = 0.0f;
        #pragma unroll
        for (int nt = 0; nt < 4; nt++) {
            int col = n0 + nt * 8 + (lane & 3) * 2;
            float w0 = __ldg(Wa2 + col), w1 = __ldg(Wa2 + col + 1);
            float e0 = __ldg(ba1 + col), e1 = __ldg(ba1 + col + 1);
            r0 += tanhf(acc[mt][nt][0] + e0) * w0 + tanhf(acc[mt][nt][1] + e1) * w1;
            r1 += tanhf(acc[mt][nt][2] + e0) * w0 + tanhf(acc[mt][nt][3] + e1) * w1;
        }
        r0 += __shfl_xor_sync(0xffffffffu, r0, 1);
        r0 += __shfl_xor_sync(0xffffffffu, r0, 2);
        r1 += __shfl_xor_sync(0xffffffffu, r1, 1);
        r1 += __shfl_xor_sync(0xffffffffu, r1, 2);
        if ((lane & 3) == 0) {
            int row = m0 + mt * 16 + (lane >> 2);
            spart[row * 5 + (wid & 3)]       = r0;
            spart[(row + 8) * 5 + (wid & 3)] = r1;
        }
    }
    __syncthreads();
    if (tid < 64) {
        float v = spart[tid * 5 + 0] + spart[tid * 5 + 1]
                + spart[tid * 5 + 2] + spart[tid * 5 + 3] + __ldg(ba2);
        g_logits[bm + tid] = v;
    }
}

// ---------------------------------------------------------------------------
// Finalize: per-batch masked softmax pooling + dynamic top-k mean
// ---------------------------------------------------------------------------
__device__ __forceinline__ float block_sum(float v, float* red) {
    const int lane = threadIdx.x & 31, warp = threadIdx.x >> 5;
    #pragma unroll
    for (int o = 16; o; o >>= 1) v += __shfl_xor_sync(0xffffffffu, v, o);
    __syncthreads();
    if (lane == 0) red[warp] = v;
    __syncthreads();
    if (warp == 0) {
        float t = red[lane];
        #pragma unroll
        for (int o = 16; o; o >>= 1) t += __shfl_xor_sync(0xffffffffu, t, o);
        if (lane == 0) red[0] = t;
    }
    __syncthreads();
    return red[0];
}
__device__ __forceinline__ float block_max(float v, float* red) {
    const int lane = threadIdx.x & 31, warp = threadIdx.x >> 5;
    #pragma unroll
    for (int o = 16; o; o >>= 1)
        v = fmaxf(v, __shfl_xor_sync(0xffffffffu, v, o));
    __syncthreads();
    if (lane == 0) red[warp] = v;
    __syncthreads();
    if (warp == 0) {
        float t = red[lane];
        #pragma unroll
        for (int o = 16; o; o >>= 1)
            t = fmaxf(t, __shfl_xor_sync(0xffffffffu, t, o));
        if (lane == 0) red[0] = t;
    }
    __syncthreads();
    return red[0];
}

__global__ __launch_bounds__(1024) void finalize_kernel(
        const int* __restrict__ lengths, float* __restrict__ out) {
    __shared__ float s_sc[NN];
    __shared__ float s_red[32];
    const int b = blockIdx.x, tid = threadIdx.x;
    const int T = lengths[b];
    const float* scores = out + BB + (size_t)b * NN;
    const float* logits = g_logits + (size_t)b * NN;

    const float sc0 = scores[tid],        sc1 = scores[tid + 1024];
    const float lg0 = logits[tid],        lg1 = logits[tid + 1024];
    const bool  v0  = tid < T,            v1  = (tid + 1024) < T;
    const float ml0 = v0 ? lg0 : NEGV,    ml1 = v1 ? lg1 : NEGV;

    const float mx  = block_max(fmaxf(ml0, ml1), s_red);
    const float e0  = expf(ml0 - mx), e1 = expf(ml1 - mx);
    const float den = block_sum(e0 + e1, s_red);
    const float num = block_sum((v0 ? e0 * sc0 : 0.0f) +
                                (v1 ? e1 * sc1 : 0.0f), s_red);
    const float attn = num / den;

    s_sc[tid]        = v0 ? sc0 : NEGV;
    s_sc[tid + 1024] = v1 ? sc1 : NEGV;
    for (int k2 = 2; k2 <= NN; k2 <<= 1) {
        for (int j = k2 >> 1; j > 0; j >>= 1) {
            __syncthreads();
            #pragma unroll 1
            for (int i = tid; i < NN; i += 1024) {
                const int ixj = i ^ j;
                if (ixj > i) {
                    const float a = s_sc[i], c = s_sc[ixj];
                    const bool up = ((i & k2) == 0);
                    if ((a > c) == up) { s_sc[i] = c; s_sc[ixj] = a; }
                }
            }
        }
    }
    __syncthreads();

    int k = T / 10;
    if (k < 1) k = 1;
    float ts = 0.0f;
    if (tid < k) ts = s_sc[NN - 1 - tid];
    const float tsum = block_sum(ts, s_red);

    if (tid == 0)
        out[b] = (T > 0) ? 0.5f * attn + 0.5f * (tsum / (float)k) : 0.0f;
}

// ---------------------------------------------------------------------------
extern "C" void kernel_launch(void* const* d_in, const int* in_sizes, int n_in,
                              void* d_out, int out_size) {
    const float* x    = (const float*)d_in[0];
    const int*   lens = (const int*)  d_in[1];
    const float* W1   = (const float*)d_in[2];
    const float* b1   = (const float*)d_in[3];
    const float* ln_g = (const float*)d_in[4];
    const float* ln_b = (const float*)d_in[5];
    const float* Wa1  = (const float*)d_in[6];
    const float* ba1  = (const float*)d_in[7];
    const float* Wa2  = (const float*)d_in[8];
    const float* ba2  = (const float*)d_in[9];
    const float* Wc   = (const float*)d_in[10];
    const float* bc   = (const float*)d_in[11];
    float* out = (float*)d_out;

    // idempotent, executes immediately (not stream-captured)
    cudaFuncSetAttribute(gemm1_kernel,
                         cudaFuncAttributeMaxDynamicSharedMemorySize, SM1);
    cudaFuncSetAttribute(gemm2_kernel,
                         cudaFuncAttributeMaxDynamicSharedMemorySize, SM2);

    convert_w1_kernel<<<HDIM * DDIM / 1024, 256>>>(W1);
    convert_wa_kernel<<<ADIM * HDIM / 1024, 256>>>(Wa1);
    gemm1_kernel<<<MTOT / 64, 256, SM1>>>(x, b1, ln_g, ln_b, Wc, bc, out);
    gemm2_kernel<<<MTOT / 64, 256, SM2>>>(ba1, Wa2, ba2);
    finalize_kernel<<<BB, 1024>>>(lens, out);
}

// round 6
// speedup vs baseline: 4.3222x; 1.6448x over previous
#include <cuda_runtime.h>
#include <cuda_fp16.h>
#include <math.h>
#include <cstdint>

#define MTOT 32768   // B*N rows
#define DDIM 1024
#define HDIM 256
#define ADIM 128
#define BB   16
#define NN   2048
#define NEGV (-1e9f)

// ---------------------------------------------------------------------------
// Scratch (__device__ globals; allocation-free rule)
// ---------------------------------------------------------------------------
__device__ __align__(1024) __half g_wh[(size_t)HDIM * DDIM];    // W1 fp16 (rounded)
__device__ __align__(1024) __half g_wah[(size_t)ADIM * HDIM];   // Wa1 fp16 hi
__device__ __align__(1024) __half g_wal[(size_t)ADIM * HDIM];   // Wa1 fp16 lo
__device__ __align__(1024) __half g_hf[(size_t)MTOT * HDIM];    // h fp16 (rounded)
__device__ __align__(1024) float  g_logits[MTOT];

// ---------------------------------------------------------------------------
// Helpers (base sm_100 target: mma.sync / ldmatrix / cp.async only)
// ---------------------------------------------------------------------------
__device__ __forceinline__ uint32_t smem_u32(const void* p) {
    uint32_t r;
    asm("{ .reg .u64 t; cvta.to.shared.u64 t, %1; cvt.u32.u64 %0, t; }"
        : "=r"(r) : "l"(p));
    return r;
}
__device__ __forceinline__ void cpa16(uint32_t dst, const void* src) {
    asm volatile("cp.async.cg.shared.global [%0], [%1], 16;"
                 :: "r"(dst), "l"(src) : "memory");
}
#define CP_COMMIT() asm volatile("cp.async.commit_group;" ::: "memory")
#define CP_WAIT0()  asm volatile("cp.async.wait_group 0;" ::: "memory")

__device__ __forceinline__ void ldsm4(uint32_t* r, uint32_t a) {
    asm volatile("ldmatrix.sync.aligned.m8n8.x4.shared.b16 {%0,%1,%2,%3}, [%4];"
                 : "=r"(r[0]), "=r"(r[1]), "=r"(r[2]), "=r"(r[3]) : "r"(a));
}
__device__ __forceinline__ void mmah(float* c, const uint32_t* a,
                                     uint32_t b0, uint32_t b1) {
    asm volatile(
        "mma.sync.aligned.m16n8k16.row.col.f32.f16.f16.f32 "
        "{%0,%1,%2,%3}, {%4,%5,%6,%7}, {%8,%9}, {%0,%1,%2,%3};"
        : "+f"(c[0]), "+f"(c[1]), "+f"(c[2]), "+f"(c[3])
        : "r"(a[0]), "r"(a[1]), "r"(a[2]), "r"(a[3]), "r"(b0), "r"(b1));
}
__device__ __forceinline__ uint32_t sw64(uint32_t off) {
    return off ^ ((off >> 3) & 0x30);
}
__device__ __forceinline__ uint32_t pkh2(__half a, __half b) {
    __half2 t = __halves2half2(a, b);   // .x = a = low 16 bits
    return *reinterpret_cast<uint32_t*>(&t);
}
__device__ __forceinline__ float gelu_exact(float y) {
    return 0.5f * y * (1.0f + erff(y * 0.70710678118654752f));
}

// ---------------------------------------------------------------------------
// Weight conversion
// ---------------------------------------------------------------------------
__global__ __launch_bounds__(256) void convert_w1_kernel(const float* __restrict__ s) {
    size_t i = (size_t)blockIdx.x * 256 + threadIdx.x;
    float4 v = reinterpret_cast<const float4*>(s)[i];
    __half2* dst = reinterpret_cast<__half2*>(g_wh);
    dst[2 * i]     = __floats2half2_rn(v.x, v.y);
    dst[2 * i + 1] = __floats2half2_rn(v.z, v.w);
}
__global__ __launch_bounds__(256) void convert_wa_kernel(const float* __restrict__ s) {
    size_t i = (size_t)blockIdx.x * 256 + threadIdx.x;
    float4 v = reinterpret_cast<const float4*>(s)[i];
    float va[4] = {v.x, v.y, v.z, v.w};
    __half h[4], l[4];
    #pragma unroll
    for (int j = 0; j < 4; j++) {
        h[j] = __float2half_rn(va[j]);
        l[j] = __float2half_rn(va[j] - __half2float(h[j]));
    }
    __half2* dh = reinterpret_cast<__half2*>(g_wah);
    __half2* dl = reinterpret_cast<__half2*>(g_wal);
    dh[2 * i]     = __halves2half2(h[0], h[1]);
    dh[2 * i + 1] = __halves2half2(h[2], h[3]);
    dl[2 * i]     = __halves2half2(l[0], l[1]);
    dl[2 * i + 1] = __halves2half2(l[2], l[3]);
}

// ---------------------------------------------------------------------------
// GEMM1 + LN + GELU + instance score, fused.
// C = x(32768x1024) @ W1^T(1024x256): BM=64, BN=256(full), KC=32, 256 thr.
// fp16 2-term split of x: acc += xh*wh + xl*wh  (fp32 accum via mma.sync)
// Per-stage smem: Ahi[0,4K) Alo[4K,8K) Bh[8K,24K)
// ---------------------------------------------------------------------------
#define ST1 24576
#define SM1 66560   // epilogue staging 64*260*4 dominates

__device__ __forceinline__ void cp_w1(uint32_t sb, int c) {
    const int t = threadIdx.x;
    #pragma unroll
    for (int i = 0; i < 4; i++) {
        int a = t + i * 256;           // atom 0..1023: 256 n-rows x 4 atoms
        int row = a >> 2, ac = a & 3;
        uint32_t sw = sw64(row * 64 + ac * 16);
        cpa16(sb + 8192 + sw, g_wh + (size_t)row * DDIM + c * 32 + ac * 8);
    }
}

__global__ __launch_bounds__(256, 2) void gemm1_kernel(
        const float* __restrict__ x, const float* __restrict__ b1,
        const float* __restrict__ ln_g, const float* __restrict__ ln_b,
        const float* __restrict__ Wc, const float* __restrict__ bc,
        float* __restrict__ out) {
    extern __shared__ __align__(1024) char smem[];
    const uint32_t sbu = smem_u32(smem);
    const int tid = threadIdx.x, lane = tid & 31, wid = tid >> 5;
    const int bm = blockIdx.x * 64;
    const int arow = tid >> 2, akq = (tid & 3) * 8;   // A-load mapping

    float4 ra, rb;
    {   // prologue: chunk 0
        const float* src = x + (size_t)(bm + arow) * DDIM + akq;
        ra = *(const float4*)src; rb = *(const float4*)(src + 4);
        cp_w1(sbu, 0);
        CP_COMMIT();
    }

    float acc[4][4][4];
    #pragma unroll
    for (int i = 0; i < 4; i++)
        #pragma unroll
        for (int j = 0; j < 4; j++)
            #pragma unroll
            for (int k = 0; k < 4; k++) acc[i][j][k] = 0.0f;

    const int n0 = wid * 32;

    for (int c = 0; c < 32; c++) {
        const uint32_t stg = (uint32_t)(c & 1) * ST1;
        {   // split+store A for chunk c (regs were prefetched)
            uint32_t off = sw64(arow * 64 + (tid & 3) * 16);
            float va[8] = {ra.x, ra.y, ra.z, ra.w, rb.x, rb.y, rb.z, rb.w};
            uint4 hv, lv;
            uint32_t* hp = (uint32_t*)&hv;
            uint32_t* lp = (uint32_t*)&lv;
            #pragma unroll
            for (int j = 0; j < 4; j++) {
                float a = va[2 * j], b = va[2 * j + 1];
                __half ha = __float2half_rn(a), hb = __float2half_rn(b);
                hp[j] = pkh2(ha, hb);
                lp[j] = pkh2(__float2half_rn(a - __half2float(ha)),
                             __float2half_rn(b - __half2float(hb)));
            }
            *(uint4*)(smem + stg + off) = hv;
            *(uint4*)(smem + stg + 4096 + off) = lv;
        }
        CP_WAIT0();
        __syncthreads();
        if (c < 31) {   // prefetch chunk c+1
            const float* src = x + (size_t)(bm + arow) * DDIM + (c + 1) * 32 + akq;
            ra = *(const float4*)src; rb = *(const float4*)(src + 4);
            cp_w1(sbu + (uint32_t)((c & 1) ^ 1) * ST1, c + 1);
            CP_COMMIT();
        }
        #pragma unroll
        for (int k16 = 0; k16 < 2; k16++) {
            uint32_t aH[4][4], aL[4][4], bH[2][4];
            #pragma unroll
            for (int mt = 0; mt < 4; mt++) {
                uint32_t off = (uint32_t)((mt * 16 + ((lane >> 3) & 1) * 8 + (lane & 7)) * 64
                               + k16 * 32 + ((lane >> 4) & 1) * 16);
                uint32_t sw = sw64(off);
                ldsm4(aH[mt], sbu + stg + sw);
                ldsm4(aL[mt], sbu + stg + 4096 + sw);
            }
            #pragma unroll
            for (int bp = 0; bp < 2; bp++) {
                uint32_t off = (uint32_t)((n0 + bp * 16 + ((lane >> 4) & 1) * 8 + (lane & 7)) * 64
                               + k16 * 32 + ((lane >> 3) & 1) * 16);
                ldsm4(bH[bp], sbu + stg + 8192 + sw64(off));
            }
            #pragma unroll
            for (int mt = 0; mt < 4; mt++)
                #pragma unroll
                for (int nt = 0; nt < 4; nt++) {
                    uint32_t h0 = bH[nt >> 1][(nt & 1) * 2];
                    uint32_t h1 = bH[nt >> 1][(nt & 1) * 2 + 1];
                    mmah(acc[mt][nt], aH[mt], h0, h1);
                    mmah(acc[mt][nt], aL[mt], h0, h1);
                }
        }
    }
    __syncthreads();

    // ---- epilogue: stage accums (64 x 256, stride 260), per-row LN+GELU ----
    float* sacc = (float*)smem;
    #pragma unroll
    for (int mt = 0; mt < 4; mt++)
        #pragma unroll
        for (int nt = 0; nt < 4; nt++) {
            int row = mt * 16 + (lane >> 2);
            int col = n0 + nt * 8 + (lane & 3) * 2;
            sacc[row * 260 + col]           = acc[mt][nt][0];
            sacc[row * 260 + col + 1]       = acc[mt][nt][1];
            sacc[(row + 8) * 260 + col]     = acc[mt][nt][2];
            sacc[(row + 8) * 260 + col + 1] = acc[mt][nt][3];
        }
    __syncthreads();

    #pragma unroll 1
    for (int it = 0; it < 8; it++) {
        const int row = it * 8 + wid;
        const int grow = bm + row;
        float v[8], s = 0.0f, q = 0.0f;
        #pragma unroll
        for (int i = 0; i < 8; i++) {
            int col = lane + 32 * i;
            v[i] = sacc[row * 260 + col] + __ldg(b1 + col);
            s += v[i]; q += v[i] * v[i];
        }
        #pragma unroll
        for (int o = 16; o; o >>= 1) {
            s += __shfl_xor_sync(0xffffffffu, s, o);
            q += __shfl_xor_sync(0xffffffffu, q, o);
        }
        const float mean = s * (1.0f / 256.0f);
        const float var  = q * (1.0f / 256.0f) - mean * mean;
        const float rstd = rsqrtf(var + 1e-5f);
        float sc = 0.0f;
        #pragma unroll
        for (int i = 0; i < 8; i++) {
            int col = lane + 32 * i;
            float y = (v[i] - mean) * rstd * __ldg(ln_g + col) + __ldg(ln_b + col);
            y = gelu_exact(y);
            sc += y * __ldg(Wc + col);
            g_hf[(size_t)grow * HDIM + col] = __float2half_rn(y);
        }
        #pragma unroll
        for (int o = 16; o; o >>= 1) sc += __shfl_xor_sync(0xffffffffu, sc, o);
        if (lane == 0) out[BB + grow] = sc + __ldg(bc);
    }
}

// ---------------------------------------------------------------------------
// GEMM2 + tanh + Wa2 reduce, fused.  logits = tanh(h@Wa1^T + ba1).Wa2 + ba2
// M=32768, N=128(full), K=256: BM=64, BN=128, KC=32, 256 thr (2m x 4n warps)
// A = h fp16 (single), B = Wa1 split hi/lo. 2 MMAs per tile.
// Per-stage smem: A[0,4K) Bh[4K,12K) Bl[12K,20K)
// ---------------------------------------------------------------------------
#define ST2 20480
#define SM2 (2 * ST2)

__device__ __forceinline__ void cp_h2(uint32_t sb, int c, int bm) {
    const int t = threadIdx.x;
    {   // A: 64 rows x 4 atoms = 256
        int row = t >> 2, ac = t & 3;
        uint32_t sw = sw64(row * 64 + ac * 16);
        cpa16(sb + sw, g_hf + (size_t)(bm + row) * HDIM + c * 32 + ac * 8);
    }
    #pragma unroll
    for (int i = 0; i < 2; i++) {      // B: 128 rows x 4 atoms = 512
        int a = t + i * 256;
        int row = a >> 2, ac = a & 3;
        uint32_t sw = sw64(row * 64 + ac * 16);
        cpa16(sb + 4096 + sw,  g_wah + (size_t)row * HDIM + c * 32 + ac * 8);
        cpa16(sb + 12288 + sw, g_wal + (size_t)row * HDIM + c * 32 + ac * 8);
    }
}

__global__ __launch_bounds__(256, 2) void gemm2_kernel(
        const float* __restrict__ ba1, const float* __restrict__ Wa2,
        const float* __restrict__ ba2) {
    extern __shared__ __align__(1024) char smem[];
    const uint32_t sbu = smem_u32(smem);
    const int tid = threadIdx.x, lane = tid & 31, wid = tid >> 5;
    const int bm = blockIdx.x * 64;
    const int m0 = (wid >> 2) * 32, n0 = (wid & 3) * 32;

    cp_h2(sbu, 0, bm);
    CP_COMMIT();

    float acc[2][4][4];
    #pragma unroll
    for (int i = 0; i < 2; i++)
        #pragma unroll
        for (int j = 0; j < 4; j++)
            #pragma unroll
            for (int k = 0; k < 4; k++) acc[i][j][k] = 0.0f;

    for (int c = 0; c < 8; c++) {
        const uint32_t stg = (uint32_t)(c & 1) * ST2;
        CP_WAIT0();
        __syncthreads();
        if (c < 7) {
            cp_h2(sbu + (uint32_t)((c & 1) ^ 1) * ST2, c + 1, bm);
            CP_COMMIT();
        }
        #pragma unroll
        for (int k16 = 0; k16 < 2; k16++) {
            uint32_t aF[2][4], bH[2][4], bL[2][4];
            #pragma unroll
            for (int mt = 0; mt < 2; mt++) {
                uint32_t off = (uint32_t)((m0 + mt * 16 + ((lane >> 3) & 1) * 8 + (lane & 7)) * 64
                               + k16 * 32 + ((lane >> 4) & 1) * 16);
                ldsm4(aF[mt], sbu + stg + sw64(off));
            }
            #pragma unroll
            for (int bp = 0; bp < 2; bp++) {
                uint32_t off = (uint32_t)((n0 + bp * 16 + ((lane >> 4) & 1) * 8 + (lane & 7)) * 64
                               + k16 * 32 + ((lane >> 3) & 1) * 16);
                uint32_t sw = sw64(off);
                ldsm4(bH[bp], sbu + stg + 4096 + sw);
                ldsm4(bL[bp], sbu + stg + 12288 + sw);
            }
            #pragma unroll
            for (int mt = 0; mt < 2; mt++)
                #pragma unroll
                for (int nt = 0; nt < 4; nt++) {
                    uint32_t h0 = bH[nt >> 1][(nt & 1) * 2];
                    uint32_t h1 = bH[nt >> 1][(nt & 1) * 2 + 1];
                    uint32_t l0 = bL[nt >> 1][(nt & 1) * 2];
                    uint32_t l1 = bL[nt >> 1][(nt & 1) * 2 + 1];
                    mmah(acc[mt][nt], aF[mt], h0, h1);
                    mmah(acc[mt][nt], aF[mt], l0, l1);
                }
        }
    }
    __syncthreads();

    // ---- epilogue: tanh(.+ba1)*Wa2, reduce over n, cross-warp via smem ----
    float* spart = (float*)smem;   // [64][5] padded
    #pragma unroll
    for (int mt = 0; mt < 2; mt++) {
        float r0 = 0.0f, r1 = 0.0f;
        #pragma unroll
        for (int nt = 0; nt < 4; nt++) {
            int col = n0 + nt * 8 + (lane & 3) * 2;
            float w0 = __ldg(Wa2 + col), w1 = __ldg(Wa2 + col + 1);
            float e0 = __ldg(ba1 + col), e1 = __ldg(ba1 + col + 1);
            r0 += tanhf(acc[mt][nt][0] + e0) * w0 + tanhf(acc[mt][nt][1] + e1) * w1;
            r1 += tanhf(acc[mt][nt][2] + e0) * w0 + tanhf(acc[mt][nt][3] + e1) * w1;
        }
        r0 += __shfl_xor_sync(0xffffffffu, r0, 1);
        r0 += __shfl_xor_sync(0xffffffffu, r0, 2);
        r1 += __shfl_xor_sync(0xffffffffu, r1, 1);
        r1 += __shfl_xor_sync(0xffffffffu, r1, 2);
        if ((lane & 3) == 0) {
            int row = m0 + mt * 16 + (lane >> 2);
            spart[row * 5 + (wid & 3)]       = r0;
            spart[(row + 8) * 5 + (wid & 3)] = r1;
        }
    }
    __syncthreads();
    if (tid < 64) {
        float v = spart[tid * 5 + 0] + spart[tid * 5 + 1]
                + spart[tid * 5 + 2] + spart[tid * 5 + 3] + __ldg(ba2);
        g_logits[bm + tid] = v;
    }
}

// ---------------------------------------------------------------------------
// Finalize: masked softmax pooling + dynamic top-k via 4-round radix-select
// ---------------------------------------------------------------------------
__device__ __forceinline__ float block_sum(float v, float* red) {
    const int lane = threadIdx.x & 31, warp = threadIdx.x >> 5;
    #pragma unroll
    for (int o = 16; o; o >>= 1) v += __shfl_xor_sync(0xffffffffu, v, o);
    __syncthreads();
    if (lane == 0) red[warp] = v;
    __syncthreads();
    if (warp == 0) {
        float t = red[lane];
        #pragma unroll
        for (int o = 16; o; o >>= 1) t += __shfl_xor_sync(0xffffffffu, t, o);
        if (lane == 0) red[0] = t;
    }
    __syncthreads();
    return red[0];
}
__device__ __forceinline__ float block_max(float v, float* red) {
    const int lane = threadIdx.x & 31, warp = threadIdx.x >> 5;
    #pragma unroll
    for (int o = 16; o; o >>= 1)
        v = fmaxf(v, __shfl_xor_sync(0xffffffffu, v, o));
    __syncthreads();
    if (lane == 0) red[warp] = v;
    __syncthreads();
    if (warp == 0) {
        float t = red[lane];
        #pragma unroll
        for (int o = 16; o; o >>= 1)
            t = fmaxf(t, __shfl_xor_sync(0xffffffffu, t, o));
        if (lane == 0) red[0] = t;
    }
    __syncthreads();
    return red[0];
}
__device__ __forceinline__ uint32_t fkey(float f, bool valid) {
    uint32_t u = __float_as_uint(f);
    u = (u & 0x80000000u) ? ~u : (u | 0x80000000u);
    return valid ? u : 0u;
}

__global__ __launch_bounds__(1024) void finalize_kernel(
        const int* __restrict__ lengths, float* __restrict__ out) {
    __shared__ float s_red[32];
    __shared__ uint32_t s_hist[256];
    __shared__ uint32_t s_sel[2];
    const int b = blockIdx.x, tid = threadIdx.x;
    const int T = lengths[b];
    const float* scores = out + BB + (size_t)b * NN;
    const float* logits = g_logits + (size_t)b * NN;

    const float sc0 = scores[tid],        sc1 = scores[tid + 1024];
    const float lg0 = logits[tid],        lg1 = logits[tid + 1024];
    const bool  v0  = tid < T,            v1  = (tid + 1024) < T;
    const float ml0 = v0 ? lg0 : NEGV,    ml1 = v1 ? lg1 : NEGV;

    const float mx  = block_max(fmaxf(ml0, ml1), s_red);
    const float e0  = expf(ml0 - mx), e1 = expf(ml1 - mx);
    const float den = block_sum(e0 + e1, s_red);
    const float num = block_sum((v0 ? e0 * sc0 : 0.0f) +
                                (v1 ? e1 * sc1 : 0.0f), s_red);
    const float attn = num / den;

    // ---- radix-select k-th largest (exact, with tie handling) ----
    const uint32_t k0 = fkey(sc0, v0), k1 = fkey(sc1, v1);
    int kk = T / 10;
    if (kk < 1) kk = 1;
    uint32_t prefix = 0, rem = (uint32_t)kk;

    #pragma unroll 1
    for (int shift = 24; shift >= 0; shift -= 8) {
        if (tid < 256) s_hist[tid] = 0;
        __syncthreads();
        const uint32_t msk = (shift == 24) ? 0u : (0xFFFFFFFFu << (shift + 8));
        if ((k0 & msk) == prefix) atomicAdd(&s_hist[(k0 >> shift) & 255], 1u);
        if ((k1 & msk) == prefix) atomicAdd(&s_hist[(k1 >> shift) & 255], 1u);
        __syncthreads();
        if (tid < 32) {
            const int hi = 255 - tid * 8;
            uint32_t cnt[8], csum = 0;
            #pragma unroll
            for (int i = 0; i < 8; i++) { cnt[i] = s_hist[hi - i]; csum += cnt[i]; }
            uint32_t run = csum;
            #pragma unroll
            for (int o = 1; o < 32; o <<= 1) {
                uint32_t t = __shfl_up_sync(0xffffffffu, run, o);
                if (tid >= o) run += t;
            }
            const uint32_t excl = run - csum;
            if (excl < rem && rem <= excl + csum) {
                uint32_t r = rem - excl, c2 = 0;
                #pragma unroll
                for (int i = 0; i < 8; i++) {
                    if (c2 + cnt[i] >= r) { s_sel[0] = (uint32_t)(hi - i);
                                            s_sel[1] = r - c2; break; }
                    c2 += cnt[i];
                }
            }
        }
        __syncthreads();
        prefix |= s_sel[0] << shift;
        rem = s_sel[1];
        __syncthreads();
    }

    const uint32_t tkey = prefix;
    const float thr = (tkey & 0x80000000u)
                    ? __uint_as_float(tkey ^ 0x80000000u)
                    : __uint_as_float(~tkey);
    const float sg = (k0 > tkey ? sc0 : 0.0f) + (k1 > tkey ? sc1 : 0.0f);
    const float sum_gt = block_sum(sg, s_red);
    const float tsum = sum_gt + (float)rem * thr;

    if (tid == 0)
        out[b] = (T > 0) ? 0.5f * attn + 0.5f * (tsum / (float)kk) : 0.0f;
}

// ---------------------------------------------------------------------------
extern "C" void kernel_launch(void* const* d_in, const int* in_sizes, int n_in,
                              void* d_out, int out_size) {
    const float* x    = (const float*)d_in[0];
    const int*   lens = (const int*)  d_in[1];
    const float* W1   = (const float*)d_in[2];
    const float* b1   = (const float*)d_in[3];
    const float* ln_g = (const float*)d_in[4];
    const float* ln_b = (const float*)d_in[5];
    const float* Wa1  = (const float*)d_in[6];
    const float* ba1  = (const float*)d_in[7];
    const float* Wa2  = (const float*)d_in[8];
    const float* ba2  = (const float*)d_in[9];
    const float* Wc   = (const float*)d_in[10];
    const float* bc   = (const float*)d_in[11];
    float* out = (float*)d_out;

    // idempotent, executes immediately (not stream-captured)
    cudaFuncSetAttribute(gemm1_kernel,
                         cudaFuncAttributeMaxDynamicSharedMemorySize, SM1);
    cudaFuncSetAttribute(gemm2_kernel,
                         cudaFuncAttributeMaxDynamicSharedMemorySize, SM2);

    convert_w1_kernel<<<HDIM * DDIM / 1024, 256>>>(W1);
    convert_wa_kernel<<<ADIM * HDIM / 1024, 256>>>(Wa1);
    gemm1_kernel<<<MTOT / 64, 256, SM1>>>(x, b1, ln_g, ln_b, Wc, bc, out);
    gemm2_kernel<<<MTOT / 64, 256, SM2>>>(ba1, Wa2, ba2);
    finalize_kernel<<<BB, 1024>>>(lens, out);
}

// round 7
// speedup vs baseline: 6.0638x; 1.4029x over previous
#include <cuda_runtime.h>
#include <cuda_fp16.h>
#include <math.h>
#include <cstdint>

#define MTOT 32768   // B*N rows
#define DDIM 1024
#define HDIM 256
#define ADIM 128
#define BB   16
#define NN   2048
#define NEGV (-1e9f)

// ---------------------------------------------------------------------------
// Scratch (__device__ globals; allocation-free rule)
// ---------------------------------------------------------------------------
__device__ __align__(1024) __half g_wh[(size_t)HDIM * DDIM];    // W1 fp16
__device__ __align__(1024) __half g_wah[(size_t)ADIM * HDIM];   // Wa1 fp16
__device__ __align__(1024) __half g_hf[(size_t)MTOT * HDIM];    // h fp16
__device__ __align__(1024) float  g_logits[MTOT];

// ---------------------------------------------------------------------------
// Helpers (base sm_100 target: mma.sync / ldmatrix / cp.async only)
// ---------------------------------------------------------------------------
__device__ __forceinline__ uint32_t smem_u32(const void* p) {
    uint32_t r;
    asm("{ .reg .u64 t; cvta.to.shared.u64 t, %1; cvt.u32.u64 %0, t; }"
        : "=r"(r) : "l"(p));
    return r;
}
__device__ __forceinline__ void cpa16(uint32_t dst, const void* src) {
    asm volatile("cp.async.cg.shared.global [%0], [%1], 16;"
                 :: "r"(dst), "l"(src) : "memory");
}
#define CP_COMMIT() asm volatile("cp.async.commit_group;" ::: "memory")
#define CP_WAIT0()  asm volatile("cp.async.wait_group 0;" ::: "memory")

__device__ __forceinline__ void ldsm4(uint32_t* r, uint32_t a) {
    asm volatile("ldmatrix.sync.aligned.m8n8.x4.shared.b16 {%0,%1,%2,%3}, [%4];"
                 : "=r"(r[0]), "=r"(r[1]), "=r"(r[2]), "=r"(r[3]) : "r"(a));
}
__device__ __forceinline__ void mmah(float* c, const uint32_t* a,
                                     uint32_t b0, uint32_t b1) {
    asm volatile(
        "mma.sync.aligned.m16n8k16.row.col.f32.f16.f16.f32 "
        "{%0,%1,%2,%3}, {%4,%5,%6,%7}, {%8,%9}, {%0,%1,%2,%3};"
        : "+f"(c[0]), "+f"(c[1]), "+f"(c[2]), "+f"(c[3])
        : "r"(a[0]), "r"(a[1]), "r"(a[2]), "r"(a[3]), "r"(b0), "r"(b1));
}
__device__ __forceinline__ uint32_t sw64(uint32_t off) {
    return off ^ ((off >> 3) & 0x30);
}
__device__ __forceinline__ uint32_t pkh2(__half a, __half b) {
    __half2 t = __halves2half2(a, b);   // .x = a = low 16 bits
    return *reinterpret_cast<uint32_t*>(&t);
}
__device__ __forceinline__ float gelu_exact(float y) {
    return 0.5f * y * (1.0f + erff(y * 0.70710678118654752f));
}

// ---------------------------------------------------------------------------
// Weight conversion (f32 -> fp16)
// ---------------------------------------------------------------------------
__global__ __launch_bounds__(256) void convert_w1_kernel(const float* __restrict__ s) {
    size_t i = (size_t)blockIdx.x * 256 + threadIdx.x;
    float4 v = reinterpret_cast<const float4*>(s)[i];
    __half2* dst = reinterpret_cast<__half2*>(g_wh);
    dst[2 * i]     = __floats2half2_rn(v.x, v.y);
    dst[2 * i + 1] = __floats2half2_rn(v.z, v.w);
}
__global__ __launch_bounds__(256) void convert_wa_kernel(const float* __restrict__ s) {
    size_t i = (size_t)blockIdx.x * 256 + threadIdx.x;
    float4 v = reinterpret_cast<const float4*>(s)[i];
    __half2* dst = reinterpret_cast<__half2*>(g_wah);
    dst[2 * i]     = __floats2half2_rn(v.x, v.y);
    dst[2 * i + 1] = __floats2half2_rn(v.z, v.w);
}

// ---------------------------------------------------------------------------
// GEMM1 + LN + GELU + instance score, fused.
// C = x(32768x1024) @ W1^T(1024x256): BM=64, BN=256(full), KC=32, 256 thr.
// Single-pass fp16 (x and W1 both rounded). fp32 accum via mma.sync.
// Per-stage smem: A[0,4K) B[4K,20K)
// ---------------------------------------------------------------------------
#define ST1 20480
#define SM1 66560   // epilogue staging 64*260*4 dominates

__device__ __forceinline__ void cp_w1(uint32_t sb, int c) {
    const int t = threadIdx.x;
    #pragma unroll
    for (int i = 0; i < 4; i++) {
        int a = t + i * 256;           // atom 0..1023: 256 n-rows x 4 atoms
        int row = a >> 2, ac = a & 3;
        uint32_t sw = sw64(row * 64 + ac * 16);
        cpa16(sb + 4096 + sw, g_wh + (size_t)row * DDIM + c * 32 + ac * 8);
    }
}

__global__ __launch_bounds__(256, 2) void gemm1_kernel(
        const float* __restrict__ x, const float* __restrict__ b1,
        const float* __restrict__ ln_g, const float* __restrict__ ln_b,
        const float* __restrict__ Wc, const float* __restrict__ bc,
        float* __restrict__ out) {
    extern __shared__ __align__(1024) char smem[];
    const uint32_t sbu = smem_u32(smem);
    const int tid = threadIdx.x, lane = tid & 31, wid = tid >> 5;
    const int bm = blockIdx.x * 64;
    const int arow = tid >> 2, akq = (tid & 3) * 8;   // A-load mapping

    float4 ra, rb;
    {   // prologue: chunk 0
        const float* src = x + (size_t)(bm + arow) * DDIM + akq;
        ra = *(const float4*)src; rb = *(const float4*)(src + 4);
        cp_w1(sbu, 0);
        CP_COMMIT();
    }

    float acc[4][4][4];
    #pragma unroll
    for (int i = 0; i < 4; i++)
        #pragma unroll
        for (int j = 0; j < 4; j++)
            #pragma unroll
            for (int k = 0; k < 4; k++) acc[i][j][k] = 0.0f;

    const int n0 = wid * 32;

    for (int c = 0; c < 32; c++) {
        const uint32_t stg = (uint32_t)(c & 1) * ST1;
        {   // convert+store A for chunk c (regs were prefetched)
            uint32_t off = sw64(arow * 64 + (tid & 3) * 16);
            uint4 hv;
            uint32_t* hp = (uint32_t*)&hv;
            hp[0] = pkh2(__float2half_rn(ra.x), __float2half_rn(ra.y));
            hp[1] = pkh2(__float2half_rn(ra.z), __float2half_rn(ra.w));
            hp[2] = pkh2(__float2half_rn(rb.x), __float2half_rn(rb.y));
            hp[3] = pkh2(__float2half_rn(rb.z), __float2half_rn(rb.w));
            *(uint4*)(smem + stg + off) = hv;
        }
        CP_WAIT0();
        __syncthreads();
        if (c < 31) {   // prefetch chunk c+1
            const float* src = x + (size_t)(bm + arow) * DDIM + (c + 1) * 32 + akq;
            ra = *(const float4*)src; rb = *(const float4*)(src + 4);
            cp_w1(sbu + (uint32_t)((c & 1) ^ 1) * ST1, c + 1);
            CP_COMMIT();
        }
        #pragma unroll
        for (int k16 = 0; k16 < 2; k16++) {
            uint32_t aF[4][4], bF[2][4];
            #pragma unroll
            for (int mt = 0; mt < 4; mt++) {
                uint32_t off = (uint32_t)((mt * 16 + ((lane >> 3) & 1) * 8 + (lane & 7)) * 64
                               + k16 * 32 + ((lane >> 4) & 1) * 16);
                ldsm4(aF[mt], sbu + stg + sw64(off));
            }
            #pragma unroll
            for (int bp = 0; bp < 2; bp++) {
                uint32_t off = (uint32_t)((n0 + bp * 16 + ((lane >> 4) & 1) * 8 + (lane & 7)) * 64
                               + k16 * 32 + ((lane >> 3) & 1) * 16);
                ldsm4(bF[bp], sbu + stg + 4096 + sw64(off));
            }
            #pragma unroll
            for (int mt = 0; mt < 4; mt++)
                #pragma unroll
                for (int nt = 0; nt < 4; nt++)
                    mmah(acc[mt][nt], aF[mt],
                         bF[nt >> 1][(nt & 1) * 2], bF[nt >> 1][(nt & 1) * 2 + 1]);
        }
    }
    __syncthreads();

    // ---- epilogue: stage accums (64 x 256, stride 260), per-row LN+GELU ----
    float* sacc = (float*)smem;
    #pragma unroll
    for (int mt = 0; mt < 4; mt++)
        #pragma unroll
        for (int nt = 0; nt < 4; nt++) {
            int row = mt * 16 + (lane >> 2);
            int col = n0 + nt * 8 + (lane & 3) * 2;
            sacc[row * 260 + col]           = acc[mt][nt][0];
            sacc[row * 260 + col + 1]       = acc[mt][nt][1];
            sacc[(row + 8) * 260 + col]     = acc[mt][nt][2];
            sacc[(row + 8) * 260 + col + 1] = acc[mt][nt][3];
        }
    __syncthreads();

    #pragma unroll 1
    for (int it = 0; it < 8; it++) {
        const int row = it * 8 + wid;
        const int grow = bm + row;
        float v[8], s = 0.0f, q = 0.0f;
        #pragma unroll
        for (int i = 0; i < 8; i++) {
            int col = lane + 32 * i;
            v[i] = sacc[row * 260 + col] + __ldg(b1 + col);
            s += v[i]; q += v[i] * v[i];
        }
        #pragma unroll
        for (int o = 16; o; o >>= 1) {
            s += __shfl_xor_sync(0xffffffffu, s, o);
            q += __shfl_xor_sync(0xffffffffu, q, o);
        }
        const float mean = s * (1.0f / 256.0f);
        const float var  = q * (1.0f / 256.0f) - mean * mean;
        const float rstd = rsqrtf(var + 1e-5f);
        float sc = 0.0f;
        #pragma unroll
        for (int i = 0; i < 8; i++) {
            int col = lane + 32 * i;
            float y = (v[i] - mean) * rstd * __ldg(ln_g + col) + __ldg(ln_b + col);
            y = gelu_exact(y);
            sc += y * __ldg(Wc + col);
            g_hf[(size_t)grow * HDIM + col] = __float2half_rn(y);
        }
        #pragma unroll
        for (int o = 16; o; o >>= 1) sc += __shfl_xor_sync(0xffffffffu, sc, o);
        if (lane == 0) out[BB + grow] = sc + __ldg(bc);
    }
}

// ---------------------------------------------------------------------------
// GEMM2 + tanh + Wa2 reduce, fused.  logits = tanh(h@Wa1^T + ba1).Wa2 + ba2
// M=32768, N=128(full), K=256: BM=64, BN=128, KC=32, 256 thr (2m x 4n warps)
// Single-pass fp16. Per-stage smem: A[0,4K) B[4K,12K)
// ---------------------------------------------------------------------------
#define ST2 12288
#define SM2 (2 * ST2)

__device__ __forceinline__ void cp_h2(uint32_t sb, int c, int bm) {
    const int t = threadIdx.x;
    {   // A: 64 rows x 4 atoms = 256
        int row = t >> 2, ac = t & 3;
        uint32_t sw = sw64(row * 64 + ac * 16);
        cpa16(sb + sw, g_hf + (size_t)(bm + row) * HDIM + c * 32 + ac * 8);
    }
    #pragma unroll
    for (int i = 0; i < 2; i++) {      // B: 128 rows x 4 atoms = 512
        int a = t + i * 256;
        int row = a >> 2, ac = a & 3;
        uint32_t sw = sw64(row * 64 + ac * 16);
        cpa16(sb + 4096 + sw, g_wah + (size_t)row * HDIM + c * 32 + ac * 8);
    }
}

__global__ __launch_bounds__(256, 2) void gemm2_kernel(
        const float* __restrict__ ba1, const float* __restrict__ Wa2,
        const float* __restrict__ ba2) {
    extern __shared__ __align__(1024) char smem[];
    const uint32_t sbu = smem_u32(smem);
    const int tid = threadIdx.x, lane = tid & 31, wid = tid >> 5;
    const int bm = blockIdx.x * 64;
    const int m0 = (wid >> 2) * 32, n0 = (wid & 3) * 32;

    cp_h2(sbu, 0, bm);
    CP_COMMIT();

    float acc[2][4][4];
    #pragma unroll
    for (int i = 0; i < 2; i++)
        #pragma unroll
        for (int j = 0; j < 4; j++)
            #pragma unroll
            for (int k = 0; k < 4; k++) acc[i][j][k] = 0.0f;

    for (int c = 0; c < 8; c++) {
        const uint32_t stg = (uint32_t)(c & 1) * ST2;
        CP_WAIT0();
        __syncthreads();
        if (c < 7) {
            cp_h2(sbu + (uint32_t)((c & 1) ^ 1) * ST2, c + 1, bm);
            CP_COMMIT();
        }
        #pragma unroll
        for (int k16 = 0; k16 < 2; k16++) {
            uint32_t aF[2][4], bF[2][4];
            #pragma unroll
            for (int mt = 0; mt < 2; mt++) {
                uint32_t off = (uint32_t)((m0 + mt * 16 + ((lane >> 3) & 1) * 8 + (lane & 7)) * 64
                               + k16 * 32 + ((lane >> 4) & 1) * 16);
                ldsm4(aF[mt], sbu + stg + sw64(off));
            }
            #pragma unroll
            for (int bp = 0; bp < 2; bp++) {
                uint32_t off = (uint32_t)((n0 + bp * 16 + ((lane >> 4) & 1) * 8 + (lane & 7)) * 64
                               + k16 * 32 + ((lane >> 3) & 1) * 16);
                ldsm4(bF[bp], sbu + stg + 4096 + sw64(off));
            }
            #pragma unroll
            for (int mt = 0; mt < 2; mt++)
                #pragma unroll
                for (int nt = 0; nt < 4; nt++)
                    mmah(acc[mt][nt], aF[mt],
                         bF[nt >> 1][(nt & 1) * 2], bF[nt >> 1][(nt & 1) * 2 + 1]);
        }
    }
    __syncthreads();

    // ---- epilogue: tanh(.+ba1)*Wa2, reduce over n, cross-warp via smem ----
    float* spart = (float*)smem;   // [64][5] padded
    #pragma unroll
    for (int mt = 0; mt < 2; mt++) {
        float r0 = 0.0f, r1 = 0.0f;
        #pragma unroll
        for (int nt = 0; nt < 4; nt++) {
            int col = n0 + nt * 8 + (lane & 3) * 2;
            float w0 = __ldg(Wa2 + col), w1 = __ldg(Wa2 + col + 1);
            float e0 = __ldg(ba1 + col), e1 = __ldg(ba1 + col + 1);
            r0 += tanhf(acc[mt][nt][0] + e0) * w0 + tanhf(acc[mt][nt][1] + e1) * w1;
            r1 += tanhf(acc[mt][nt][2] + e0) * w0 + tanhf(acc[mt][nt][3] + e1) * w1;
        }
        r0 += __shfl_xor_sync(0xffffffffu, r0, 1);
        r0 += __shfl_xor_sync(0xffffffffu, r0, 2);
        r1 += __shfl_xor_sync(0xffffffffu, r1, 1);
        r1 += __shfl_xor_sync(0xffffffffu, r1, 2);
        if ((lane & 3) == 0) {
            int row = m0 + mt * 16 + (lane >> 2);
            spart[row * 5 + (wid & 3)]       = r0;
            spart[(row + 8) * 5 + (wid & 3)] = r1;
        }
    }
    __syncthreads();
    if (tid < 64) {
        float v = spart[tid * 5 + 0] + spart[tid * 5 + 1]
                + spart[tid * 5 + 2] + spart[tid * 5 + 3] + __ldg(ba2);
        g_logits[bm + tid] = v;
    }
}

// ---------------------------------------------------------------------------
// Finalize: masked softmax pooling + dynamic top-k via 4-round radix-select
// ---------------------------------------------------------------------------
__device__ __forceinline__ float block_sum(float v, float* red) {
    const int lane = threadIdx.x & 31, warp = threadIdx.x >> 5;
    #pragma unroll
    for (int o = 16; o; o >>= 1) v += __shfl_xor_sync(0xffffffffu, v, o);
    __syncthreads();
    if (lane == 0) red[warp] = v;
    __syncthreads();
    if (warp == 0) {
        float t = red[lane];
        #pragma unroll
        for (int o = 16; o; o >>= 1) t += __shfl_xor_sync(0xffffffffu, t, o);
        if (lane == 0) red[0] = t;
    }
    __syncthreads();
    return red[0];
}
__device__ __forceinline__ float block_max(float v, float* red) {
    const int lane = threadIdx.x & 31, warp = threadIdx.x >> 5;
    #pragma unroll
    for (int o = 16; o; o >>= 1)
        v = fmaxf(v, __shfl_xor_sync(0xffffffffu, v, o));
    __syncthreads();
    if (lane == 0) red[warp] = v;
    __syncthreads();
    if (warp == 0) {
        float t = red[lane];
        #pragma unroll
        for (int o = 16; o; o >>= 1)
            t = fmaxf(t, __shfl_xor_sync(0xffffffffu, t, o));
        if (lane == 0) red[0] = t;
    }
    __syncthreads();
    return red[0];
}
__device__ __forceinline__ uint32_t fkey(float f, bool valid) {
    uint32_t u = __float_as_uint(f);
    u = (u & 0x80000000u) ? ~u : (u | 0x80000000u);
    return valid ? u : 0u;
}

__global__ __launch_bounds__(1024) void finalize_kernel(
        const int* __restrict__ lengths, float* __restrict__ out) {
    __shared__ float s_red[32];
    __shared__ uint32_t s_hist[256];
    __shared__ uint32_t s_sel[2];
    const int b = blockIdx.x, tid = threadIdx.x;
    const int T = lengths[b];
    const float* scores = out + BB + (size_t)b * NN;
    const float* logits = g_logits + (size_t)b * NN;

    const float sc0 = scores[tid],        sc1 = scores[tid + 1024];
    const float lg0 = logits[tid],        lg1 = logits[tid + 1024];
    const bool  v0  = tid < T,            v1  = (tid + 1024) < T;
    const float ml0 = v0 ? lg0 : NEGV,    ml1 = v1 ? lg1 : NEGV;

    const float mx  = block_max(fmaxf(ml0, ml1), s_red);
    const float e0  = expf(ml0 - mx), e1 = expf(ml1 - mx);
    const float den = block_sum(e0 + e1, s_red);
    const float num = block_sum((v0 ? e0 * sc0 : 0.0f) +
                                (v1 ? e1 * sc1 : 0.0f), s_red);
    const float attn = num / den;

    // ---- radix-select k-th largest (exact, with tie handling) ----
    const uint32_t k0 = fkey(sc0, v0), k1 = fkey(sc1, v1);
    int kk = T / 10;
    if (kk < 1) kk = 1;
    uint32_t prefix = 0, rem = (uint32_t)kk;

    #pragma unroll 1
    for (int shift = 24; shift >= 0; shift -= 8) {
        if (tid < 256) s_hist[tid] = 0;
        __syncthreads();
        const uint32_t msk = (shift == 24) ? 0u : (0xFFFFFFFFu << (shift + 8));
        if ((k0 & msk) == prefix) atomicAdd(&s_hist[(k0 >> shift) & 255], 1u);
        if ((k1 & msk) == prefix) atomicAdd(&s_hist[(k1 >> shift) & 255], 1u);
        __syncthreads();
        if (tid < 32) {
            const int hi = 255 - tid * 8;
            uint32_t cnt[8], csum = 0;
            #pragma unroll
            for (int i = 0; i < 8; i++) { cnt[i] = s_hist[hi - i]; csum += cnt[i]; }
            uint32_t run = csum;
            #pragma unroll
            for (int o = 1; o < 32; o <<= 1) {
                uint32_t t = __shfl_up_sync(0xffffffffu, run, o);
                if (tid >= o) run += t;
            }
            const uint32_t excl = run - csum;
            if (excl < rem && rem <= excl + csum) {
                uint32_t r = rem - excl, c2 = 0;
                #pragma unroll
                for (int i = 0; i < 8; i++) {
                    if (c2 + cnt[i] >= r) { s_sel[0] = (uint32_t)(hi - i);
                                            s_sel[1] = r - c2; break; }
                    c2 += cnt[i];
                }
            }
        }
        __syncthreads();
        prefix |= s_sel[0] << shift;
        rem = s_sel[1];
        __syncthreads();
    }

    const uint32_t tkey = prefix;
    const float thr = (tkey & 0x80000000u)
                    ? __uint_as_float(tkey ^ 0x80000000u)
                    : __uint_as_float(~tkey);
    const float sg = (k0 > tkey ? sc0 : 0.0f) + (k1 > tkey ? sc1 : 0.0f);
    const float sum_gt = block_sum(sg, s_red);
    const float tsum = sum_gt + (float)rem * thr;

    if (tid == 0)
        out[b] = (T > 0) ? 0.5f * attn + 0.5f * (tsum / (float)kk) : 0.0f;
}

// ---------------------------------------------------------------------------
extern "C" void kernel_launch(void* const* d_in, const int* in_sizes, int n_in,
                              void* d_out, int out_size) {
    const float* x    = (const float*)d_in[0];
    const int*   lens = (const int*)  d_in[1];
    const float* W1   = (const float*)d_in[2];
    const float* b1   = (const float*)d_in[3];
    const float* ln_g = (const float*)d_in[4];
    const float* ln_b = (const float*)d_in[5];
    const float* Wa1  = (const float*)d_in[6];
    const float* ba1  = (const float*)d_in[7];
    const float* Wa2  = (const float*)d_in[8];
    const float* ba2  = (const float*)d_in[9];
    const float* Wc   = (const float*)d_in[10];
    const float* bc   = (const float*)d_in[11];
    float* out = (float*)d_out;

    // idempotent, executes immediately (not stream-captured)
    cudaFuncSetAttribute(gemm1_kernel,
                         cudaFuncAttributeMaxDynamicSharedMemorySize, SM1);
    cudaFuncSetAttribute(gemm2_kernel,
                         cudaFuncAttributeMaxDynamicSharedMemorySize, SM2);

    convert_w1_kernel<<<HDIM * DDIM / 1024, 256>>>(W1);
    convert_wa_kernel<<<ADIM * HDIM / 1024, 256>>>(Wa1);
    gemm1_kernel<<<MTOT / 64, 256, SM1>>>(x, b1, ln_g, ln_b, Wc, bc, out);
    gemm2_kernel<<<MTOT / 64, 256, SM2>>>(ba1, Wa2, ba2);
    finalize_kernel<<<BB, 1024>>>(lens, out);
}